// round 3
// baseline (speedup 1.0000x reference)
#include <cuda_runtime.h>
#include <math.h>

#define NN    100000
#define NE    1200000
#define F_IN  64
#define F_HID 16
#define F_OUT 40

// ---- scratch (static device globals; referenced ONLY from device code) ----
__device__ float g_xs  [NN * F_HID];   // x @ W1_self + b1
__device__ float g_xn  [NN * F_HID];   // x @ W1_neigh
__device__ float g_agg1[NN * F_HID];   // segment-sum of xn[src] onto dst
__device__ float g_agg2[NN * F_HID];   // segment-sum of h[src]  onto dst
__device__ float g_h   [NN * F_HID];   // hidden activations
__device__ float g_deg [NN];           // in-degree (float)

// ---------------------------------------------------------------------------
// Kernel 1: per-node linear projections for layer 1 (+ zero the accumulators)
//   xs = x @ W1_self + b1 ;  xn = x @ W1_neigh
// ---------------------------------------------------------------------------
__global__ __launch_bounds__(256)
void k_lin1(const float* __restrict__ x,
            const float* __restrict__ W1s,
            const float* __restrict__ W1n,
            const float* __restrict__ b1,
            int n)
{
    __shared__ float4 sWs[F_IN * (F_HID / 4)];   // [k][jb]
    __shared__ float4 sWn[F_IN * (F_HID / 4)];
    for (int i = threadIdx.x; i < F_IN * F_HID; i += blockDim.x) {
        ((float*)sWs)[i] = W1s[i];
        ((float*)sWn)[i] = W1n[i];
    }
    __syncthreads();

    int node = blockIdx.x * blockDim.x + threadIdx.x;
    if (node >= n) return;

    // zero the atomic accumulators and degree for this replay
    float4 z = make_float4(0.f, 0.f, 0.f, 0.f);
    float4* a1 = (float4*)g_agg1 + node * 4;
    float4* a2 = (float4*)g_agg2 + node * 4;
#pragma unroll
    for (int jb = 0; jb < 4; jb++) { a1[jb] = z; a2[jb] = z; }
    g_deg[node] = 0.f;

    float4 accS[4], accN[4];
    const float4* b1v = (const float4*)b1;
#pragma unroll
    for (int jb = 0; jb < 4; jb++) { accS[jb] = __ldg(b1v + jb); accN[jb] = z; }

    const float4* xrow = (const float4*)x + node * (F_IN / 4);
#pragma unroll 1
    for (int kb = 0; kb < F_IN / 4; kb++) {
        float4 xv = __ldg(xrow + kb);
        float xk[4] = { xv.x, xv.y, xv.z, xv.w };
#pragma unroll
        for (int kk = 0; kk < 4; kk++) {
            int k = kb * 4 + kk;
            float xs = xk[kk];
#pragma unroll
            for (int jb = 0; jb < 4; jb++) {
                float4 ws = sWs[k * 4 + jb];
                float4 wn = sWn[k * 4 + jb];
                accS[jb].x += xs * ws.x; accS[jb].y += xs * ws.y;
                accS[jb].z += xs * ws.z; accS[jb].w += xs * ws.w;
                accN[jb].x += xs * wn.x; accN[jb].y += xs * wn.y;
                accN[jb].z += xs * wn.z; accN[jb].w += xs * wn.w;
            }
        }
    }

    float4* xsrow = (float4*)g_xs + node * 4;
    float4* xnrow = (float4*)g_xn + node * 4;
#pragma unroll
    for (int jb = 0; jb < 4; jb++) { xsrow[jb] = accS[jb]; xnrow[jb] = accN[jb]; }
}

// ---------------------------------------------------------------------------
// Edge aggregation, layer 1:  g_agg1[dst] += g_xn[src];  g_deg[dst] += 1
// (g_* referenced directly in device code -> correct device addresses)
// ---------------------------------------------------------------------------
__global__ __launch_bounds__(256)
void k_edge1(const int* __restrict__ ei, int e)
{
    int t = blockIdx.x * blockDim.x + threadIdx.x;
    if (t >= e) return;
    int src = __ldg(ei + t);
    int dst = __ldg(ei + e + t);

    const float4* row = (const float4*)g_xn + src * 4;
    float4 v0 = row[0];
    float4 v1 = row[1];
    float4 v2 = row[2];
    float4 v3 = row[3];

    float* d = g_agg1 + dst * F_HID;
    atomicAdd(d + 0,  v0.x); atomicAdd(d + 1,  v0.y);
    atomicAdd(d + 2,  v0.z); atomicAdd(d + 3,  v0.w);
    atomicAdd(d + 4,  v1.x); atomicAdd(d + 5,  v1.y);
    atomicAdd(d + 6,  v1.z); atomicAdd(d + 7,  v1.w);
    atomicAdd(d + 8,  v2.x); atomicAdd(d + 9,  v2.y);
    atomicAdd(d + 10, v2.z); atomicAdd(d + 11, v2.w);
    atomicAdd(d + 12, v3.x); atomicAdd(d + 13, v3.y);
    atomicAdd(d + 14, v3.z); atomicAdd(d + 15, v3.w);

    atomicAdd(g_deg + dst, 1.0f);
}

// ---------------------------------------------------------------------------
// Edge aggregation, layer 2:  g_agg2[dst] += g_h[src]
// ---------------------------------------------------------------------------
__global__ __launch_bounds__(256)
void k_edge2(const int* __restrict__ ei, int e)
{
    int t = blockIdx.x * blockDim.x + threadIdx.x;
    if (t >= e) return;
    int src = __ldg(ei + t);
    int dst = __ldg(ei + e + t);

    const float4* row = (const float4*)g_h + src * 4;
    float4 v0 = row[0];
    float4 v1 = row[1];
    float4 v2 = row[2];
    float4 v3 = row[3];

    float* d = g_agg2 + dst * F_HID;
    atomicAdd(d + 0,  v0.x); atomicAdd(d + 1,  v0.y);
    atomicAdd(d + 2,  v0.z); atomicAdd(d + 3,  v0.w);
    atomicAdd(d + 4,  v1.x); atomicAdd(d + 5,  v1.y);
    atomicAdd(d + 6,  v1.z); atomicAdd(d + 7,  v1.w);
    atomicAdd(d + 8,  v2.x); atomicAdd(d + 9,  v2.y);
    atomicAdd(d + 10, v2.z); atomicAdd(d + 11, v2.w);
    atomicAdd(d + 12, v3.x); atomicAdd(d + 13, v3.y);
    atomicAdd(d + 14, v3.z); atomicAdd(d + 15, v3.w);
}

// ---------------------------------------------------------------------------
// Kernel 3: h = relu(xs + agg1 / max(deg,1))
// ---------------------------------------------------------------------------
__global__ __launch_bounds__(256)
void k_hid(int n)
{
    int node = blockIdx.x * blockDim.x + threadIdx.x;
    if (node >= n) return;
    float invd = 1.0f / fmaxf(g_deg[node], 1.0f);
    const float4* s = (const float4*)g_xs   + node * 4;
    const float4* a = (const float4*)g_agg1 + node * 4;
    float4* h = (float4*)g_h + node * 4;
#pragma unroll
    for (int jb = 0; jb < 4; jb++) {
        float4 sv = s[jb], av = a[jb], r;
        r.x = fmaxf(sv.x + av.x * invd, 0.f);
        r.y = fmaxf(sv.y + av.y * invd, 0.f);
        r.z = fmaxf(sv.z + av.z * invd, 0.f);
        r.w = fmaxf(sv.w + av.w * invd, 0.f);
        h[jb] = r;
    }
}

// ---------------------------------------------------------------------------
// Kernel 5: out = log_softmax(h @ W2s + (agg2/deg) @ W2n + b2)
// ---------------------------------------------------------------------------
__global__ __launch_bounds__(256)
void k_out(const float* __restrict__ W2s,
           const float* __restrict__ W2n,
           const float* __restrict__ b2,
           float* __restrict__ out,
           int n)
{
    __shared__ float4 sWs[F_HID * (F_OUT / 4)];   // [k][jb], jb in 0..9
    __shared__ float4 sWn[F_HID * (F_OUT / 4)];
    __shared__ float4 sb[F_OUT / 4];
    for (int i = threadIdx.x; i < F_HID * F_OUT; i += blockDim.x) {
        ((float*)sWs)[i] = W2s[i];
        ((float*)sWn)[i] = W2n[i];
    }
    for (int i = threadIdx.x; i < F_OUT; i += blockDim.x) ((float*)sb)[i] = b2[i];
    __syncthreads();

    int node = blockIdx.x * blockDim.x + threadIdx.x;
    if (node >= n) return;

    float invd = 1.0f / fmaxf(g_deg[node], 1.0f);

    float hk[F_HID], ak[F_HID];
    const float4* hrow = (const float4*)g_h    + node * 4;
    const float4* arow = (const float4*)g_agg2 + node * 4;
#pragma unroll
    for (int jb = 0; jb < 4; jb++) {
        float4 hv = hrow[jb];
        float4 av = arow[jb];
        hk[jb*4+0] = hv.x; hk[jb*4+1] = hv.y; hk[jb*4+2] = hv.z; hk[jb*4+3] = hv.w;
        ak[jb*4+0] = av.x * invd; ak[jb*4+1] = av.y * invd;
        ak[jb*4+2] = av.z * invd; ak[jb*4+3] = av.w * invd;
    }

    float4 acc[F_OUT / 4];
#pragma unroll
    for (int jb = 0; jb < F_OUT / 4; jb++) acc[jb] = sb[jb];

#pragma unroll
    for (int k = 0; k < F_HID; k++) {
        float hv = hk[k], av = ak[k];
#pragma unroll
        for (int jb = 0; jb < F_OUT / 4; jb++) {
            float4 ws = sWs[k * (F_OUT / 4) + jb];
            float4 wn = sWn[k * (F_OUT / 4) + jb];
            acc[jb].x += hv * ws.x + av * wn.x;
            acc[jb].y += hv * ws.y + av * wn.y;
            acc[jb].z += hv * ws.z + av * wn.z;
            acc[jb].w += hv * ws.w + av * wn.w;
        }
    }

    // log-softmax over 40 columns
    float m = -1e30f;
#pragma unroll
    for (int jb = 0; jb < F_OUT / 4; jb++) {
        m = fmaxf(m, fmaxf(fmaxf(acc[jb].x, acc[jb].y), fmaxf(acc[jb].z, acc[jb].w)));
    }
    float ssum = 0.f;
#pragma unroll
    for (int jb = 0; jb < F_OUT / 4; jb++) {
        ssum += expf(acc[jb].x - m) + expf(acc[jb].y - m)
              + expf(acc[jb].z - m) + expf(acc[jb].w - m);
    }
    float lse = m + logf(ssum);

    float4* orow = (float4*)(out + (size_t)node * F_OUT);
#pragma unroll
    for (int jb = 0; jb < F_OUT / 4; jb++) {
        float4 r;
        r.x = acc[jb].x - lse; r.y = acc[jb].y - lse;
        r.z = acc[jb].z - lse; r.w = acc[jb].w - lse;
        orow[jb] = r;
    }
}

// ---------------------------------------------------------------------------
extern "C" void kernel_launch(void* const* d_in, const int* in_sizes, int n_in,
                              void* d_out, int out_size)
{
    const float* x   = (const float*)d_in[0];
    const int*   ei  = (const int*)  d_in[1];
    const float* W1s = (const float*)d_in[2];
    const float* W1n = (const float*)d_in[3];
    const float* b1  = (const float*)d_in[4];
    const float* W2s = (const float*)d_in[5];
    const float* W2n = (const float*)d_in[6];
    const float* b2  = (const float*)d_in[7];
    float* out = (float*)d_out;

    int n = in_sizes[0] / F_IN;   // 100000
    int e = in_sizes[1] / 2;      // 1200000

    const int TB = 256;
    int nb_node = (n + TB - 1) / TB;
    int nb_edge = (e + TB - 1) / TB;

    k_lin1 <<<nb_node, TB>>>(x, W1s, W1n, b1, n);
    k_edge1<<<nb_edge, TB>>>(ei, e);
    k_hid  <<<nb_node, TB>>>(n);
    k_edge2<<<nb_edge, TB>>>(ei, e);
    k_out  <<<nb_node, TB>>>(W2s, W2n, b2, out, n);
}

// round 4
// speedup vs baseline: 2.1761x; 2.1761x over previous
#include <cuda_runtime.h>
#include <math.h>

#define NN    100000
#define NE    1200000
#define F_IN  64
#define F_HID 16
#define F_OUT 40

#define SCAN_BS 1024
#define NBLK    ((NN + SCAN_BS - 1) / SCAN_BS)   // 98

// ---- scratch (static device globals; referenced ONLY from device code) ----
__device__ float g_xs  [NN * F_HID];   // x @ W1_self + b1
__device__ float g_xn  [NN * F_HID];   // x @ W1_neigh
__device__ float g_h   [NN * F_HID];   // hidden activations
__device__ float g_agg2[NN * F_HID];   // layer-2 neighbor sums (plain stores)
__device__ int   g_cnt   [NN];         // in-degree
__device__ int   g_off   [NN];         // CSR offsets (exclusive scan of cnt)
__device__ int   g_cursor[NN];         // scatter cursors
__device__ int   g_eidx  [NE];         // src ids bucketed by dst
__device__ int   g_bsum  [128];        // scan block sums

// ---------------------------------------------------------------------------
// Kernel 1: layer-1 projections (+ zero the degree counters)
//   xs = x @ W1_self + b1 ;  xn = x @ W1_neigh
// ---------------------------------------------------------------------------
__global__ __launch_bounds__(256)
void k_lin1(const float* __restrict__ x,
            const float* __restrict__ W1s,
            const float* __restrict__ W1n,
            const float* __restrict__ b1,
            int n)
{
    __shared__ float4 sWs[F_IN * (F_HID / 4)];   // [k][jb]
    __shared__ float4 sWn[F_IN * (F_HID / 4)];
    for (int i = threadIdx.x; i < F_IN * F_HID; i += blockDim.x) {
        ((float*)sWs)[i] = W1s[i];
        ((float*)sWn)[i] = W1n[i];
    }
    __syncthreads();

    int node = blockIdx.x * blockDim.x + threadIdx.x;
    if (node >= n) return;

    g_cnt[node] = 0;

    float4 z = make_float4(0.f, 0.f, 0.f, 0.f);
    float4 accS[4], accN[4];
    const float4* b1v = (const float4*)b1;
#pragma unroll
    for (int jb = 0; jb < 4; jb++) { accS[jb] = __ldg(b1v + jb); accN[jb] = z; }

    const float4* xrow = (const float4*)x + node * (F_IN / 4);
#pragma unroll 1
    for (int kb = 0; kb < F_IN / 4; kb++) {
        float4 xv = __ldg(xrow + kb);
        float xk[4] = { xv.x, xv.y, xv.z, xv.w };
#pragma unroll
        for (int kk = 0; kk < 4; kk++) {
            int k = kb * 4 + kk;
            float xs = xk[kk];
#pragma unroll
            for (int jb = 0; jb < 4; jb++) {
                float4 ws = sWs[k * 4 + jb];
                float4 wn = sWn[k * 4 + jb];
                accS[jb].x += xs * ws.x; accS[jb].y += xs * ws.y;
                accS[jb].z += xs * ws.z; accS[jb].w += xs * ws.w;
                accN[jb].x += xs * wn.x; accN[jb].y += xs * wn.y;
                accN[jb].z += xs * wn.z; accN[jb].w += xs * wn.w;
            }
        }
    }

    float4* xsrow = (float4*)g_xs + node * 4;
    float4* xnrow = (float4*)g_xn + node * 4;
#pragma unroll
    for (int jb = 0; jb < 4; jb++) { xsrow[jb] = accS[jb]; xnrow[jb] = accN[jb]; }
}

// ---------------------------------------------------------------------------
// CSR build step 1: degree histogram over dst
// ---------------------------------------------------------------------------
__global__ __launch_bounds__(256)
void k_count(const int* __restrict__ ei, int e)
{
    int t = blockIdx.x * blockDim.x + threadIdx.x;
    if (t >= e) return;
    int dst = __ldg(ei + e + t);
    atomicAdd(g_cnt + dst, 1);
}

// ---------------------------------------------------------------------------
// CSR build step 2a: per-block inclusive scan -> exclusive-within-block + totals
// ---------------------------------------------------------------------------
__global__ __launch_bounds__(SCAN_BS)
void k_scan1()
{
    __shared__ int s[SCAN_BS];
    int i = blockIdx.x * SCAN_BS + threadIdx.x;
    int v = (i < NN) ? g_cnt[i] : 0;
    s[threadIdx.x] = v;
    __syncthreads();
#pragma unroll
    for (int off = 1; off < SCAN_BS; off <<= 1) {
        int t = (threadIdx.x >= off) ? s[threadIdx.x - off] : 0;
        __syncthreads();
        s[threadIdx.x] += t;
        __syncthreads();
    }
    if (i < NN) g_off[i] = s[threadIdx.x] - v;          // exclusive within block
    if (threadIdx.x == SCAN_BS - 1) g_bsum[blockIdx.x] = s[SCAN_BS - 1];
}

// ---------------------------------------------------------------------------
// CSR build step 2b: exclusive scan of the block totals (NBLK <= 128)
// ---------------------------------------------------------------------------
__global__ __launch_bounds__(128)
void k_scan2()
{
    __shared__ int s[128];
    int v = (threadIdx.x < NBLK) ? g_bsum[threadIdx.x] : 0;
    s[threadIdx.x] = v;
    __syncthreads();
#pragma unroll
    for (int off = 1; off < 128; off <<= 1) {
        int t = (threadIdx.x >= off) ? s[threadIdx.x - off] : 0;
        __syncthreads();
        s[threadIdx.x] += t;
        __syncthreads();
    }
    if (threadIdx.x < NBLK) g_bsum[threadIdx.x] = s[threadIdx.x] - v;  // exclusive
}

// ---------------------------------------------------------------------------
// CSR build step 2c: add block offsets; init scatter cursors
// ---------------------------------------------------------------------------
__global__ __launch_bounds__(256)
void k_scan3(int n)
{
    int i = blockIdx.x * blockDim.x + threadIdx.x;
    if (i >= n) return;
    int o = g_off[i] + g_bsum[i / SCAN_BS];
    g_off[i] = o;
    g_cursor[i] = o;
}

// ---------------------------------------------------------------------------
// CSR build step 3: scatter src ids into dst buckets
// ---------------------------------------------------------------------------
__global__ __launch_bounds__(256)
void k_scatter(const int* __restrict__ ei, int e)
{
    int t = blockIdx.x * blockDim.x + threadIdx.x;
    if (t >= e) return;
    int src = __ldg(ei + t);
    int dst = __ldg(ei + e + t);
    int slot = atomicAdd(g_cursor + dst, 1);
    g_eidx[slot] = src;
}

// ---------------------------------------------------------------------------
// Layer-1 aggregation (warp per node), fused with hidden activation:
//   h = relu(xs + mean_neigh(xn))
// Lane layout: nb = lane>>2 (8 neighbor slots), jb = lane&3 (float4 column)
// ---------------------------------------------------------------------------
__global__ __launch_bounds__(256)
void k_agg1(int n)
{
    int warp = (blockIdx.x * blockDim.x + threadIdx.x) >> 5;
    if (warp >= n) return;
    int lane = threadIdx.x & 31;
    int nb = lane >> 2;
    int jb = lane & 3;

    int beg = g_off[warp];
    int deg = g_cnt[warp];
    int end = beg + deg;

    float4 acc = make_float4(0.f, 0.f, 0.f, 0.f);
    for (int i = beg + nb; i < end; i += 8) {
        int s = g_eidx[i];
        float4 v = ((const float4*)g_xn)[s * 4 + jb];
        acc.x += v.x; acc.y += v.y; acc.z += v.z; acc.w += v.w;
    }
#pragma unroll
    for (int off = 4; off < 32; off <<= 1) {
        acc.x += __shfl_xor_sync(0xffffffffu, acc.x, off);
        acc.y += __shfl_xor_sync(0xffffffffu, acc.y, off);
        acc.z += __shfl_xor_sync(0xffffffffu, acc.z, off);
        acc.w += __shfl_xor_sync(0xffffffffu, acc.w, off);
    }

    if (nb == 0) {
        float invd = 1.0f / fmaxf((float)deg, 1.0f);
        float4 sv = ((const float4*)g_xs)[warp * 4 + jb];
        float4 r;
        r.x = fmaxf(sv.x + acc.x * invd, 0.f);
        r.y = fmaxf(sv.y + acc.y * invd, 0.f);
        r.z = fmaxf(sv.z + acc.z * invd, 0.f);
        r.w = fmaxf(sv.w + acc.w * invd, 0.f);
        ((float4*)g_h)[warp * 4 + jb] = r;
    }
}

// ---------------------------------------------------------------------------
// Layer-2 aggregation (warp per node): agg2 = sum_neigh(h)  (plain stores)
// ---------------------------------------------------------------------------
__global__ __launch_bounds__(256)
void k_agg2(int n)
{
    int warp = (blockIdx.x * blockDim.x + threadIdx.x) >> 5;
    if (warp >= n) return;
    int lane = threadIdx.x & 31;
    int nb = lane >> 2;
    int jb = lane & 3;

    int beg = g_off[warp];
    int end = beg + g_cnt[warp];

    float4 acc = make_float4(0.f, 0.f, 0.f, 0.f);
    for (int i = beg + nb; i < end; i += 8) {
        int s = g_eidx[i];
        float4 v = ((const float4*)g_h)[s * 4 + jb];
        acc.x += v.x; acc.y += v.y; acc.z += v.z; acc.w += v.w;
    }
#pragma unroll
    for (int off = 4; off < 32; off <<= 1) {
        acc.x += __shfl_xor_sync(0xffffffffu, acc.x, off);
        acc.y += __shfl_xor_sync(0xffffffffu, acc.y, off);
        acc.z += __shfl_xor_sync(0xffffffffu, acc.z, off);
        acc.w += __shfl_xor_sync(0xffffffffu, acc.w, off);
    }
    if (nb == 0) ((float4*)g_agg2)[warp * 4 + jb] = acc;
}

// ---------------------------------------------------------------------------
// Output: out = log_softmax(h @ W2s + (agg2/deg) @ W2n + b2)
// ---------------------------------------------------------------------------
__global__ __launch_bounds__(256)
void k_out(const float* __restrict__ W2s,
           const float* __restrict__ W2n,
           const float* __restrict__ b2,
           float* __restrict__ out,
           int n)
{
    __shared__ float4 sWs[F_HID * (F_OUT / 4)];
    __shared__ float4 sWn[F_HID * (F_OUT / 4)];
    __shared__ float4 sb[F_OUT / 4];
    for (int i = threadIdx.x; i < F_HID * F_OUT; i += blockDim.x) {
        ((float*)sWs)[i] = W2s[i];
        ((float*)sWn)[i] = W2n[i];
    }
    for (int i = threadIdx.x; i < F_OUT; i += blockDim.x) ((float*)sb)[i] = b2[i];
    __syncthreads();

    int node = blockIdx.x * blockDim.x + threadIdx.x;
    if (node >= n) return;

    float invd = 1.0f / fmaxf((float)g_cnt[node], 1.0f);

    float hk[F_HID], ak[F_HID];
    const float4* hrow = (const float4*)g_h    + node * 4;
    const float4* arow = (const float4*)g_agg2 + node * 4;
#pragma unroll
    for (int jb = 0; jb < 4; jb++) {
        float4 hv = hrow[jb];
        float4 av = arow[jb];
        hk[jb*4+0] = hv.x; hk[jb*4+1] = hv.y; hk[jb*4+2] = hv.z; hk[jb*4+3] = hv.w;
        ak[jb*4+0] = av.x * invd; ak[jb*4+1] = av.y * invd;
        ak[jb*4+2] = av.z * invd; ak[jb*4+3] = av.w * invd;
    }

    float4 acc[F_OUT / 4];
#pragma unroll
    for (int jb = 0; jb < F_OUT / 4; jb++) acc[jb] = sb[jb];

#pragma unroll
    for (int k = 0; k < F_HID; k++) {
        float hv = hk[k], av = ak[k];
#pragma unroll
        for (int jb = 0; jb < F_OUT / 4; jb++) {
            float4 ws = sWs[k * (F_OUT / 4) + jb];
            float4 wn = sWn[k * (F_OUT / 4) + jb];
            acc[jb].x += hv * ws.x + av * wn.x;
            acc[jb].y += hv * ws.y + av * wn.y;
            acc[jb].z += hv * ws.z + av * wn.z;
            acc[jb].w += hv * ws.w + av * wn.w;
        }
    }

    float m = -1e30f;
#pragma unroll
    for (int jb = 0; jb < F_OUT / 4; jb++) {
        m = fmaxf(m, fmaxf(fmaxf(acc[jb].x, acc[jb].y), fmaxf(acc[jb].z, acc[jb].w)));
    }
    float ssum = 0.f;
#pragma unroll
    for (int jb = 0; jb < F_OUT / 4; jb++) {
        ssum += expf(acc[jb].x - m) + expf(acc[jb].y - m)
              + expf(acc[jb].z - m) + expf(acc[jb].w - m);
    }
    float lse = m + logf(ssum);

    float4* orow = (float4*)(out + (size_t)node * F_OUT);
#pragma unroll
    for (int jb = 0; jb < F_OUT / 4; jb++) {
        float4 r;
        r.x = acc[jb].x - lse; r.y = acc[jb].y - lse;
        r.z = acc[jb].z - lse; r.w = acc[jb].w - lse;
        orow[jb] = r;
    }
}

// ---------------------------------------------------------------------------
extern "C" void kernel_launch(void* const* d_in, const int* in_sizes, int n_in,
                              void* d_out, int out_size)
{
    const float* x   = (const float*)d_in[0];
    const int*   ei  = (const int*)  d_in[1];
    const float* W1s = (const float*)d_in[2];
    const float* W1n = (const float*)d_in[3];
    const float* b1  = (const float*)d_in[4];
    const float* W2s = (const float*)d_in[5];
    const float* W2n = (const float*)d_in[6];
    const float* b2  = (const float*)d_in[7];
    float* out = (float*)d_out;

    int n = in_sizes[0] / F_IN;   // 100000
    int e = in_sizes[1] / 2;      // 1200000

    const int TB = 256;
    int nb_node = (n + TB - 1) / TB;
    int nb_edge = (e + TB - 1) / TB;
    int nb_warp = (n * 32 + TB - 1) / TB;   // warp-per-node kernels

    k_lin1   <<<nb_node, TB>>>(x, W1s, W1n, b1, n);
    k_count  <<<nb_edge, TB>>>(ei, e);
    k_scan1  <<<NBLK, SCAN_BS>>>();
    k_scan2  <<<1, 128>>>();
    k_scan3  <<<nb_node, TB>>>(n);
    k_scatter<<<nb_edge, TB>>>(ei, e);
    k_agg1   <<<nb_warp, TB>>>(n);
    k_agg2   <<<nb_warp, TB>>>(n);
    k_out    <<<nb_node, TB>>>(W2s, W2n, b2, out, n);
}